// round 14
// baseline (speedup 1.0000x reference)
#include <cuda_runtime.h>
#include <cuda_fp16.h>

// Problem constants (fixed by the reference)
#define VV   4096                 // vocab
#define MM   4                    // markov order
#define BB   8
#define LL   2048
#define FAN  (MM * (VV + 1))      // 16388
#define NPOS (BB * LL)            // 16384

#define TPB  512                  // threads per block (16 warps)
#define SMEM_BYTES (FAN * 4 * 2)  // __half table [FAN][4] = 131104 B

// ---------------------------------------------------------------------------
// Fused table-in-SMEM kernel. One block per vocab quad (grid = V/4 = 1024).
//  Phase 1 (load): read W rows v0..v0+3 (4 x 64 KB, coalesced, each W byte
//    read once chip-wide), quantize to fp16, store interleaved [FAN][4] in
//    dynamic smem (STS.64, 2-way conflict).
//  Phase 2 (gather): sweep all 16384 positions; per position 4 random
//    LDS.64 row lookups + pairwise HADD2 + exact fp32 bias + STG.128.
// No transposed table in global memory at all -> the 646 MB of slab L2/DRAM
// traffic from the previous architecture vanishes.
// Adjacent blockIdx.x = adjacent vocab quads run in lockstep waves, so their
// 16 B halves of each 32 B output sector merge in L2 before writeback.
// ---------------------------------------------------------------------------
__global__ __launch_bounds__(TPB, 1)
void ngram_fused_smem(const float* __restrict__ W,
                      const float* __restrict__ bias,
                      const int*   __restrict__ idx,
                      float*       __restrict__ out) {
    extern __shared__ __half s_tab[];      // [FAN][4] interleaved

    const int v0 = blockIdx.x * 4;
    const int t  = threadIdx.x;

    // ---- Phase 1: load + quantize -----------------------------------------
    // 4 coalesced scalar streams (one per vocab row); each iteration a warp
    // reads 4 x 128 B. __ldcs: W is read-once, keep L2 clean for store-merge.
    {
        const float* w0 = W + (size_t)(v0 + 0) * FAN;
        const float* w1 = W + (size_t)(v0 + 1) * FAN;
        const float* w2 = W + (size_t)(v0 + 2) * FAN;
        const float* w3 = W + (size_t)(v0 + 3) * FAN;
        for (int i = t; i < FAN; i += TPB) {
            const float x0 = __ldcs(w0 + i);
            const float x1 = __ldcs(w1 + i);
            const float x2 = __ldcs(w2 + i);
            const float x3 = __ldcs(w3 + i);
            const __half2 p0 = __floats2half2_rn(x0, x1);
            const __half2 p1 = __floats2half2_rn(x2, x3);
            uint2 o;
            o.x = *reinterpret_cast<const unsigned int*>(&p0);
            o.y = *reinterpret_cast<const unsigned int*>(&p1);
            // 8 B contiguous store at byte offset i*8 (STS.64, 2-way conflict)
            *reinterpret_cast<uint2*>(&s_tab[i * 4]) = o;
        }
    }

    // Bias for this quad, exact fp32 (added after the fp16 sums).
    const float4 bb = *reinterpret_cast<const float4*>(&bias[v0]);

    __syncthreads();

    // ---- Phase 2: gather ---------------------------------------------------
    // Thread handles positions t, t+TPB, ... (32 per thread). Consecutive
    // threads -> consecutive positions: idx loads coalesced + L1-resident.
    #pragma unroll 2
    for (int pos = t; pos < NPOS; pos += TPB) {
        const int b = pos >> 11;             // / LL
        const int l = pos & (LL - 1);        // % LL
        const int base = b * LL + l;

        const int t0 = (l >= 3) ? __ldg(&idx[base - 3]) : VV;
        const int t1 = (l >= 2) ? __ldg(&idx[base - 2]) : VV;
        const int t2 = (l >= 1) ? __ldg(&idx[base - 1]) : VV;
        const int t3 = __ldg(&idx[base]);

        // 4 random-row LDS.64 (8 B each: this quad's 4 fp16 values).
        const uint2 a0 = *reinterpret_cast<const uint2*>(&s_tab[(0 * (VV + 1) + t0) * 4]);
        const uint2 a1 = *reinterpret_cast<const uint2*>(&s_tab[(1 * (VV + 1) + t1) * 4]);
        const uint2 a2 = *reinterpret_cast<const uint2*>(&s_tab[(2 * (VV + 1) + t2) * 4]);
        const uint2 a3 = *reinterpret_cast<const uint2*>(&s_tab[(3 * (VV + 1) + t3) * 4]);

        // Pairwise fp16 adds, then finish + bias in fp32.
        const __half2 l01 = __hadd2(*reinterpret_cast<const __half2*>(&a0.x),
                                    *reinterpret_cast<const __half2*>(&a1.x));
        const __half2 l23 = __hadd2(*reinterpret_cast<const __half2*>(&a2.x),
                                    *reinterpret_cast<const __half2*>(&a3.x));
        const __half2 h01 = __hadd2(*reinterpret_cast<const __half2*>(&a0.y),
                                    *reinterpret_cast<const __half2*>(&a1.y));
        const __half2 h23 = __hadd2(*reinterpret_cast<const __half2*>(&a2.y),
                                    *reinterpret_cast<const __half2*>(&a3.y));
        const float2 fl0 = __half22float2(l01);
        const float2 fl1 = __half22float2(l23);
        const float2 fh0 = __half22float2(h01);
        const float2 fh1 = __half22float2(h23);

        float4 r;
        r.x = bb.x + (fl0.x + fl1.x);
        r.y = bb.y + (fl0.y + fl1.y);
        r.z = bb.z + (fh0.x + fh1.x);
        r.w = bb.w + (fh0.y + fh1.y);

        // 16 B store into out[pos][v0..v0+3]; sibling 16 B comes from the
        // adjacent (concurrent) vocab-quad block -> merges to full sectors.
        __stcs(reinterpret_cast<float4*>(&out[(size_t)pos * VV + v0]), r);
    }
}

// ---------------------------------------------------------------------------
// Launch: ONE kernel, grid = V/4 = 1024 blocks x 512 threads, 131 KB smem.
// Inputs identified by element count:
//   idx : B*L = 16384 (int32), bias : V = 4096, W : V*FAN (largest)
// ---------------------------------------------------------------------------
extern "C" void kernel_launch(void* const* d_in, const int* in_sizes, int n_in,
                              void* d_out, int out_size) {
    const int*   idx  = nullptr;
    const float* W    = nullptr;
    const float* bias = nullptr;

    for (int i = 0; i < n_in; i++) {
        if (in_sizes[i] == NPOS)      idx  = (const int*)d_in[i];
        else if (in_sizes[i] == VV)   bias = (const float*)d_in[i];
        else                          W    = (const float*)d_in[i];
    }

    // Opt in to >48 KB dynamic smem (idempotent host-side attribute set).
    cudaFuncSetAttribute(ngram_fused_smem,
                         cudaFuncAttributeMaxDynamicSharedMemorySize,
                         SMEM_BYTES);

    ngram_fused_smem<<<VV / 4, TPB, SMEM_BYTES>>>(W, bias, idx, (float*)d_out);
}